// round 15
// baseline (speedup 1.0000x reference)
#include <cuda_runtime.h>
#include <cuda_bf16.h>
#include <math.h>
#include <stdint.h>

namespace {
constexpr int kB = 8;
constexpr int kN = 4096;
constexpr int kD = 512;
constexpr int kL = 64;
constexpr int kKS = 8;                // split-k slices for qall/qk/zo
constexpr int kM = kB * kL;           // 512 rows through the GEMMs
constexpr int kSlab = kM * kD;        // 262144 floats per partial slab
constexpr int kNSlab = 6;             // term(3) x kz(2) partial slabs
constexpr float kInvTemp = 0.044194173824159216f; // 1/sqrt(512)
constexpr int kStageBytes = 16384;    // 8KB A + 8KB B per stage
constexpr int kSmemDyn = 4 * kStageBytes;
}

// ---------------- scratch (device globals; no allocation allowed) ----------
__device__ int   g_order[kB * kN];
__device__ int   g_nvalid[kB];
__device__ float g_qallp[kKS * kL * kD];   // z @ Wq^T partials
__device__ float g_zop[kKS * kL * kD];     // z @ Wo^T partials (empty-seg path)
__device__ float g_qkp[kKS * kL * kD];
__device__ float g_denom[kM];
__device__ __nv_bfloat16 g_Uh[kM * kD],   g_Ul[kM * kD];    // bf16 split of U
__device__ __nv_bfloat16 g_Woh[kD * kD],  g_Wol[kD * kD];   // Wo split (rows)
__device__ __nv_bfloat16 g_WvTh[kD * kD], g_WvTl[kD * kD];  // Wv^T split
__device__ __nv_bfloat16 g_Wch[kD * kD],  g_Wcl[kD * kD];   // Wc = Wo@Wv split
__device__ float g_GPA[kNSlab * kSlab];    // Wc partial slabs
__device__ float g_GP[kNSlab * kSlab];     // out partial slabs

__device__ __forceinline__ float dot4(float4 a, float4 b) {
    return a.x * b.x + a.y * b.y + a.z * b.z + a.w * b.w;
}
__device__ __forceinline__ float sum4(float4 a) { return a.x + a.y + a.z + a.w; }

__device__ __forceinline__ bool mask_at(const void* m, int idx, int kind) {
    if (kind == 1) return ((const int*)m)[idx] != 0;
    if (kind == 2) return ((const float*)m)[idx] != 0.0f;
    return ((const unsigned char*)m)[idx] != 0;
}

__device__ __forceinline__ uint32_t s2u(const void* p) {
    uint32_t a;
    asm("{ .reg .u64 t; cvta.to.shared.u64 t, %1; cvt.u32.u64 %0, t; }"
        : "=r"(a) : "l"(p));
    return a;
}
__device__ __forceinline__ void ldsm4(uint32_t addr, uint32_t r[4]) {
    asm volatile("ldmatrix.sync.aligned.m8n8.x4.shared.b16 {%0,%1,%2,%3}, [%4];"
        : "=r"(r[0]), "=r"(r[1]), "=r"(r[2]), "=r"(r[3]) : "r"(addr));
}
__device__ __forceinline__ void mma16816(float d[4], const uint32_t a[4],
                                         uint32_t b0, uint32_t b1) {
    asm volatile(
        "mma.sync.aligned.m16n8k16.row.col.f32.bf16.bf16.f32 "
        "{%0,%1,%2,%3}, {%4,%5,%6,%7}, {%8,%9}, {%0,%1,%2,%3};"
        : "+f"(d[0]), "+f"(d[1]), "+f"(d[2]), "+f"(d[3])
        : "r"(a[0]), "r"(a[1]), "r"(a[2]), "r"(a[3]), "r"(b0), "r"(b1));
}
__device__ __forceinline__ void cp16(uint32_t saddr, const void* g) {
    asm volatile("cp.async.cg.shared.global [%0], [%1], 16;"
                 :: "r"(saddr), "l"(g) : "memory");
}
__device__ __forceinline__ void cp_commit() {
    asm volatile("cp.async.commit_group;" ::: "memory");
}
template <int N>
__device__ __forceinline__ void cp_wait() {
    asm volatile("cp.async.wait_group %0;" :: "n"(N) : "memory");
}

__device__ __forceinline__ void bf16_split_store4(float4 v, __nv_bfloat16* dh,
                                                  __nv_bfloat16* dl) {
    __nv_bfloat162 h01 = __floats2bfloat162_rn(v.x, v.y);
    __nv_bfloat162 h23 = __floats2bfloat162_rn(v.z, v.w);
    float2 f01 = __bfloat1622float2(h01);
    float2 f23 = __bfloat1622float2(h23);
    __nv_bfloat162 l01 = __floats2bfloat162_rn(v.x - f01.x, v.y - f01.y);
    __nv_bfloat162 l23 = __floats2bfloat162_rn(v.z - f23.x, v.w - f23.y);
    *(__nv_bfloat162*)(dh)     = h01;
    *(__nv_bfloat162*)(dh + 2) = h23;
    *(__nv_bfloat162*)(dl)     = l01;
    *(__nv_bfloat162*)(dl + 2) = l23;
}

// ==== K1 (stream A): blocks 0..7 order; 8..71 qall; 72..135 zo ==============
__global__ __launch_bounds__(256) void k1_order_qall(const void* __restrict__ mask,
                                                     const float* __restrict__ z,
                                                     const float* __restrict__ Wq,
                                                     const float* __restrict__ Wo) {
    const int tid = threadIdx.x;
    const int wid = tid >> 5, lane = tid & 31;

    __shared__ float Asm[64][68];
    __shared__ float Bsm[64][68];

    if (blockIdx.x < kB) {
        const int b = blockIdx.x;
        const unsigned* mw = (const unsigned*)mask;
        int iok = 1, fok = 1;
        for (int i = tid; i < 1024; i += 256) {
            unsigned v = mw[b * 1024 + i];
            iok &= (v <= 1u);
            fok &= (v == 0u || v == 0x3F800000u);
        }
        iok = __syncthreads_and(iok);
        fok = __syncthreads_and(fok);
        const int kind = iok ? 1 : (fok ? 2 : 0);

        const int base = tid * 16;
        bool v[16];
        int c = 0;
#pragma unroll
        for (int j = 0; j < 16; j++) {
            v[j] = !mask_at(mask, b * kN + base + j, kind);
            c += v[j] ? 1 : 0;
        }
        int inc = c;
#pragma unroll
        for (int o = 1; o < 32; o <<= 1) {
            int x = __shfl_up_sync(0xffffffffu, inc, o);
            if (lane >= o) inc += x;
        }
        __shared__ int wsum[8], woff[8];
        if (lane == 31) wsum[wid] = inc;
        __syncthreads();
        if (tid < 8) {
            int s = 0;
            for (int w = 0; w < 8; w++) { woff[w] = s; s += wsum[w]; }
            if (tid == 0) g_nvalid[b] = s;
        }
        __syncthreads();
        int pos = woff[wid] + inc - c;
#pragma unroll
        for (int j = 0; j < 16; j++) {
            if (v[j]) g_order[b * kN + pos++] = base + j;
        }
    } else {
        const int bid2 = blockIdx.x - kB;           // 0..127
        const int which = bid2 >> 6;                 // 0 -> qall(Wq), 1 -> zo(Wo)
        const int nt = bid2 & 7, kz = (bid2 >> 3) & 7;
        const int kb = kz * 64;
        const float* W = which ? Wo : Wq;
        float* P = which ? g_zop : g_qallp;
        for (int jj = tid; jj < 1024; jj += 256) {
            const int l = jj >> 4, k4 = (jj & 15) * 4;
            float4 v = *(const float4*)(z + (size_t)l * kD + kb + k4);
            Asm[k4 + 0][l] = v.x; Asm[k4 + 1][l] = v.y;
            Asm[k4 + 2][l] = v.z; Asm[k4 + 3][l] = v.w;
        }
        for (int jj = tid; jj < 1024; jj += 256) {
            const int d = jj >> 4, k4 = (jj & 15) * 4;
            float4 v = *(const float4*)(W + (size_t)(nt * 64 + d) * kD + kb + k4);
            Bsm[k4 + 0][d] = v.x; Bsm[k4 + 1][d] = v.y;
            Bsm[k4 + 2][d] = v.z; Bsm[k4 + 3][d] = v.w;
        }
        __syncthreads();
        const int tx = tid & 15, ty = tid >> 4;
        float acc[4][4] = {};
#pragma unroll 4
        for (int k = 0; k < 64; k++) {
            float4 a = *(const float4*)&Asm[k][ty * 4];
            float4 b = *(const float4*)&Bsm[k][tx * 4];
            acc[0][0] += a.x * b.x; acc[0][1] += a.x * b.y; acc[0][2] += a.x * b.z; acc[0][3] += a.x * b.w;
            acc[1][0] += a.y * b.x; acc[1][1] += a.y * b.y; acc[1][2] += a.y * b.z; acc[1][3] += a.y * b.w;
            acc[2][0] += a.z * b.x; acc[2][1] += a.z * b.y; acc[2][2] += a.z * b.z; acc[2][3] += a.z * b.w;
            acc[3][0] += a.w * b.x; acc[3][1] += a.w * b.y; acc[3][2] += a.w * b.z; acc[3][3] += a.w * b.w;
        }
#pragma unroll
        for (int i = 0; i < 4; i++) {
            float4 v = make_float4(acc[i][0], acc[i][1], acc[i][2], acc[i][3]);
            *(float4*)&P[(size_t)kz * (kL * kD) + (size_t)(ty * 4 + i) * kD + nt * 64 + tx * 4] = v;
        }
    }
}

// ==== WS (stream B): blocks 0..63 Wo split; 64..127 Wv^T transpose-split ====
__global__ __launch_bounds__(256) void wsplitT_k(const float* __restrict__ Wv,
                                                 const float* __restrict__ Wo) {
    const int tid = threadIdx.x;
    if (blockIdx.x < 64) {
        const int lb = blockIdx.x;
#pragma unroll
        for (int it = 0; it < 4; it++) {
            const int i = lb * 4096 + it * 1024 + tid * 4;
            float4 v = *(const float4*)(Wo + i);
            bf16_split_store4(v, g_Woh + i, g_Wol + i);
        }
    } else {
        // transpose-split a 64x64 tile of Wv: WvT[j][i] = Wv[i][j]
        const int tb = blockIdx.x - 64;
        const int tr = tb >> 3, tc = tb & 7;         // tile row/col in 8x8 grid
        __shared__ float tile[64][65];
        for (int jj = tid; jj < 1024; jj += 256) {
            const int r = jj >> 4, c4 = (jj & 15) * 4;
            float4 v = *(const float4*)(Wv + (size_t)(tr * 64 + r) * kD + tc * 64 + c4);
            tile[r][c4 + 0] = v.x; tile[r][c4 + 1] = v.y;
            tile[r][c4 + 2] = v.z; tile[r][c4 + 3] = v.w;
        }
        __syncthreads();
        for (int jj = tid; jj < 1024; jj += 256) {
            const int j = jj >> 4, r4 = (jj & 15) * 4;   // output row j, cols r4..r4+3
            float4 v = make_float4(tile[r4 + 0][j], tile[r4 + 1][j],
                                   tile[r4 + 2][j], tile[r4 + 3][j]);
            const size_t o = (size_t)(tc * 64 + j) * kD + tr * 64 + r4;
            bf16_split_store4(v, g_WvTh + o, g_WvTl + o);
        }
    }
}

// ======================= K2: qk GEMM ========================================
__global__ __launch_bounds__(256) void qk_gemm(const float* __restrict__ Wk) {
    const int tid = threadIdx.x;
    const int nt = blockIdx.x & 7, kz = blockIdx.x >> 3;
    const int kb = kz * 64;
    __shared__ float Asm[64][68];
    __shared__ float Bsm[64][68];
    for (int jj = tid; jj < 1024; jj += 256) {
        const int l = jj >> 4, k4 = (jj & 15) * 4;
        float4 v = make_float4(0.f, 0.f, 0.f, 0.f);
#pragma unroll
        for (int s = 0; s < kKS; s++) {
            float4 p = *(const float4*)&g_qallp[(size_t)s * (kL * kD) + (size_t)l * kD + kb + k4];
            v.x += p.x; v.y += p.y; v.z += p.z; v.w += p.w;
        }
        Asm[k4 + 0][l] = v.x; Asm[k4 + 1][l] = v.y;
        Asm[k4 + 2][l] = v.z; Asm[k4 + 3][l] = v.w;
    }
    for (int jj = tid; jj < 1024; jj += 256) {
        const int k = jj >> 4, e4 = (jj & 15) * 4;
        float4 v = *(const float4*)(Wk + (size_t)(kb + k) * kD + nt * 64 + e4);
        *(float4*)&Bsm[k][e4] = v;
    }
    __syncthreads();
    const int tx = tid & 15, ty = tid >> 4;
    float acc[4][4] = {};
#pragma unroll 4
    for (int k = 0; k < 64; k++) {
        float4 a = *(const float4*)&Asm[k][ty * 4];
        float4 b = *(const float4*)&Bsm[k][tx * 4];
        acc[0][0] += a.x * b.x; acc[0][1] += a.x * b.y; acc[0][2] += a.x * b.z; acc[0][3] += a.x * b.w;
        acc[1][0] += a.y * b.x; acc[1][1] += a.y * b.y; acc[1][2] += a.y * b.z; acc[1][3] += a.y * b.w;
        acc[2][0] += a.z * b.x; acc[2][1] += a.z * b.y; acc[2][2] += a.z * b.z; acc[2][3] += a.z * b.w;
        acc[3][0] += a.w * b.x; acc[3][1] += a.w * b.y; acc[3][2] += a.w * b.z; acc[3][3] += a.w * b.w;
    }
#pragma unroll
    for (int i = 0; i < 4; i++) {
        float4 v = make_float4(acc[i][0], acc[i][1], acc[i][2], acc[i][3]);
        *(float4*)&g_qkp[(size_t)(kz * kL + ty * 4 + i) * kD + nt * 64 + tx * 4] = v;
    }
}

// ============ K3: fused LN + logits + segment softmax (bf16-split out) ======
__global__ __launch_bounds__(256) void attn_k(const float* __restrict__ feats) {
    const int l = blockIdx.x, b = blockIdx.y;
    const int tid = threadIdx.x, wid = tid >> 5, lane = tid & 31;

    __shared__ float qk_s[kD];
    __shared__ float s_part[8][kD];
    __shared__ float den_part[8];

    for (int e = tid; e < kD; e += 256) {
        float s = 0.f;
#pragma unroll
        for (int ks = 0; ks < kKS; ks++) s += g_qkp[(size_t)(ks * kL + l) * kD + e];
        qk_s[e] = s;
    }
    __syncthreads();

    float4 qk4[4];
    float qks = 0.f;
#pragma unroll
    for (int q = 0; q < 4; q++) {
        qk4[q] = *(const float4*)&qk_s[(lane + 32 * q) * 4];
        qks += sum4(qk4[q]);
    }
#pragma unroll
    for (int o = 16; o; o >>= 1) qks += __shfl_xor_sync(0xffffffffu, qks, o);

    const int nv = g_nvalid[b];
    int segsz = nv / kL; if (segsz < 1) segsz = 1;
    const int n_used = min(nv, kL * segsz);
    const int t0 = l * segsz;
    const int t1 = min(t0 + segsz, n_used);

    float4 sac[4];
#pragma unroll
    for (int q = 0; q < 4; q++) sac[q] = make_float4(0.f, 0.f, 0.f, 0.f);
    float dac = 0.f;

    int t = t0 + wid;
    int o_nxt = (t + 8 < t1) ? g_order[b * kN + t + 8] : 0;
    float4 v[4];
    if (t < t1) {
        const int o_cur = g_order[b * kN + t];
        const float4* row = (const float4*)(feats + ((size_t)b * kN + o_cur) * kD);
#pragma unroll
        for (int q = 0; q < 4; q++) v[q] = row[lane + 32 * q];
    }
    for (; t < t1; t += 8) {
        const int tn = t + 8;
        float4 vn[4];
        if (tn < t1) {
            const float4* rown = (const float4*)(feats + ((size_t)b * kN + o_nxt) * kD);
#pragma unroll
            for (int q = 0; q < 4; q++) vn[q] = rown[lane + 32 * q];
        }
        const int o_n2 = (tn + 8 < t1) ? g_order[b * kN + tn + 8] : 0;

        float sm = 0.f, sq = 0.f, dt = 0.f;
#pragma unroll
        for (int q = 0; q < 4; q++) {
            sm += sum4(v[q]);
            sq += dot4(v[q], v[q]);
            dt += dot4(v[q], qk4[q]);
        }
#pragma unroll
        for (int o = 16; o; o >>= 1) {
            sm += __shfl_xor_sync(0xffffffffu, sm, o);
            sq += __shfl_xor_sync(0xffffffffu, sq, o);
            dt += __shfl_xor_sync(0xffffffffu, dt, o);
        }
        const float mu = sm * (1.0f / kD);
        const float var = sq * (1.0f / kD) - mu * mu;
        const float rstd = rsqrtf(var + 1e-5f);
        float logit = (dt - mu * qks) * rstd * kInvTemp;
        logit = fminf(5.0f, fmaxf(-5.0f, logit));
        const float w = __expf(logit - 5.0f);
        const float wr = w * rstd;
        const float wm = wr * mu;
#pragma unroll
        for (int q = 0; q < 4; q++) {
            sac[q].x += wr * v[q].x - wm;
            sac[q].y += wr * v[q].y - wm;
            sac[q].z += wr * v[q].z - wm;
            sac[q].w += wr * v[q].w - wm;
        }
        dac += w;
        if (tn < t1) {
#pragma unroll
            for (int q = 0; q < 4; q++) v[q] = vn[q];
        }
        o_nxt = o_n2;
    }

#pragma unroll
    for (int q = 0; q < 4; q++)
        *(float4*)&s_part[wid][(lane + 32 * q) * 4] = sac[q];
    if (lane == 0) den_part[wid] = dac;
    __syncthreads();

    float den = 0.f;
#pragma unroll
    for (int w = 0; w < 8; w++) den += den_part[w];

    const int m = b * kL + l;
    const float inv = (den > 0.f) ? (1.0f / den) : 0.f;
    for (int e = tid; e < kD; e += 256) {
        float s = 0.f;
#pragma unroll
        for (int w = 0; w < 8; w++) s += s_part[w][e];
        const float v2 = s * inv;
        __nv_bfloat16 h = __float2bfloat16(v2);
        g_Uh[(size_t)m * kD + e] = h;
        g_Ul[(size_t)m * kD + e] = __float2bfloat16(v2 - __bfloat162float(h));
    }
    if (tid == 0) g_denom[m] = den;
}

// ====== HMMA term+K split GEMM — grid (8,8,6), fully prefetched (R10 body) ==
// G=1: Wc = Wo @ Wv (A=Wo split, B=Wv^T split) -> g_GPA slabs.
// G=2: out = U @ Wc^T (A=U split, B=Wc split)  -> g_GP slabs.
template <int G>
__global__ __launch_bounds__(256) void mma3_k() {
    extern __shared__ __align__(16) uint8_t sm[];   // 4 x (8KB A + 8KB B)
    const int tid = threadIdx.x, wid = tid >> 5, lane = tid & 31;
    const int nt = blockIdx.x, mt = blockIdx.y, zs = blockIdx.z;
    const int t = zs >> 1, kz = zs & 1;

    const __nv_bfloat16* Ahg = (G == 1) ? g_Woh : g_Uh;
    const __nv_bfloat16* Alg = (G == 1) ? g_Wol : g_Ul;
    const __nv_bfloat16* Bhg = (G == 1) ? g_WvTh : g_Wch;
    const __nv_bfloat16* Blg = (G == 1) ? g_WvTl : g_Wcl;
    const __nv_bfloat16* A = ((t < 2) ? Ahg : Alg) + (size_t)(mt * 64) * kD + kz * 256;
    const __nv_bfloat16* Bw = ((t == 1) ? Blg : Bhg) + (size_t)(nt * 64) * kD + kz * 256;

    const int lr0 = tid >> 3, lj = tid & 7;
    const int lr1 = lr0 + 32;
    const uint32_t sw0 = lr0 * 128 + ((lj ^ (lr0 & 7)) << 4);
    const uint32_t sw1 = lr1 * 128 + ((lj ^ (lr1 & 7)) << 4);
    const uint32_t smu = s2u(sm);

#pragma unroll
    for (int c = 0; c < 4; c++) {
        const uint32_t base = smu + c * kStageBytes;
        const int kk = c * 64;
        cp16(base + sw0,        A  + (size_t)lr0 * kD + kk + lj * 8);
        cp16(base + sw1,        A  + (size_t)lr1 * kD + kk + lj * 8);
        cp16(base + 8192 + sw0, Bw + (size_t)lr0 * kD + kk + lj * 8);
        cp16(base + 8192 + sw1, Bw + (size_t)lr1 * kD + kk + lj * 8);
    }
    cp_commit();

    const int wm = (wid >> 2) << 5, wn = (wid & 3) << 4;
    const int a_r0 = wm + (lane & 15);
    const int a_r1 = a_r0 + 16;
    const int a_cadd = lane >> 4;
    const int b_r = wn + (lane & 7) + ((lane >> 4) << 3);
    const int b_cadd = (lane >> 3) & 1;

    float acc[2][2][4] = {};

    cp_wait<0>();
    __syncthreads();

#pragma unroll
    for (int c = 0; c < 4; c++) {
        const uint32_t Abase = smu + c * kStageBytes;
        const uint32_t Bbase = Abase + 8192;
#pragma unroll
        for (int ks = 0; ks < 4; ks++) {
            uint32_t a0[4], a1[4], bb[4];
            const int ch = 2 * ks;
            ldsm4(Abase + a_r0 * 128 + (((ch + a_cadd) ^ (a_r0 & 7)) << 4), a0);
            ldsm4(Abase + a_r1 * 128 + (((ch + a_cadd) ^ (a_r1 & 7)) << 4), a1);
            ldsm4(Bbase + b_r * 128 + (((ch + b_cadd) ^ (b_r & 7)) << 4), bb);
            mma16816(acc[0][0], a0, bb[0], bb[1]);
            mma16816(acc[0][1], a0, bb[2], bb[3]);
            mma16816(acc[1][0], a1, bb[0], bb[1]);
            mma16816(acc[1][1], a1, bb[2], bb[3]);
        }
    }

    float* P = (G == 1 ? g_GPA : g_GP) + (size_t)zs * kSlab;
    const int g = lane >> 2, tg = lane & 3;
#pragma unroll
    for (int mf = 0; mf < 2; mf++) {
#pragma unroll
        for (int rr = 0; rr < 2; rr++) {
            const int m = mt * 64 + wm + mf * 16 + g + rr * 8;
#pragma unroll
            for (int nf = 0; nf < 2; nf++) {
                const int n = nt * 64 + wn + nf * 8 + tg * 2;
                *(float2*)(P + (size_t)m * kD + n) =
                    make_float2(acc[mf][nf][rr * 2 + 0], acc[mf][nf][rr * 2 + 1]);
            }
        }
    }
}

// ============ reduceA (stream B): g_GPA slabs -> Wc bf16 split ==============
__global__ __launch_bounds__(256) void reduceA_k() {
    const int idx = blockIdx.x * 256 + threadIdx.x;  // float4 index over 512x512
    float4 v = make_float4(0.f, 0.f, 0.f, 0.f);
#pragma unroll
    for (int s = 0; s < kNSlab; s++) {
        float4 p = ((const float4*)g_GPA)[(size_t)s * (kSlab / 4) + idx];
        v.x += p.x; v.y += p.y; v.z += p.z; v.w += p.w;
    }
    bf16_split_store4(v, g_Wch + idx * 4, g_Wcl + idx * 4);
}

// ============ fin: slab reduce + bias + den==0 / nvalid==0 replacements =====
__global__ __launch_bounds__(256) void fin_k(float* __restrict__ out,
                                             const float* __restrict__ z,
                                             const float* __restrict__ bo) {
    const int idx = blockIdx.x * 256 + threadIdx.x;  // float4 index
    const int m = idx >> 7, c4 = idx & 127;
    float4 v;
    if (g_nvalid[m >> 6] == 0) {
        v = ((const float4*)(z + (size_t)(m & (kL - 1)) * kD))[c4];
    } else {
        float4 b = ((const float4*)bo)[c4];
        if (g_denom[m] > 0.f) {
            v = b;
#pragma unroll
            for (int s = 0; s < kNSlab; s++) {
                float4 p = ((const float4*)g_GP)[(size_t)s * (kSlab / 4) + idx];
                v.x += p.x; v.y += p.y; v.z += p.z; v.w += p.w;
            }
        } else {
            // empty segment: out = z_l @ Wo^T + bo  (zo partials)
            v = b;
            const int l = m & (kL - 1);
#pragma unroll
            for (int s = 0; s < kKS; s++) {
                float4 p = *(const float4*)&g_zop[(size_t)s * (kL * kD) + (size_t)l * kD + c4 * 4];
                v.x += p.x; v.y += p.y; v.z += p.z; v.w += p.w;
            }
        }
    }
    ((float4*)out)[idx] = v;
}

// ---------------------------------------------------------------------------
extern "C" void kernel_launch(void* const* d_in, const int* in_sizes, int n_in,
                              void* d_out, int out_size) {
    (void)in_sizes; (void)n_in; (void)out_size;
    const float* feats = (const float*)d_in[0];
    // d_in[1] = coords (unused by the reference output)
    const void*  mask  = d_in[2];
    const float* z     = (const float*)d_in[3];
    const float* Wq    = (const float*)d_in[4];
    const float* Wk    = (const float*)d_in[5];
    const float* Wv    = (const float*)d_in[6];
    const float* Wo    = (const float*)d_in[7];
    const float* bo    = (const float*)d_in[8];
    float* out = (float*)d_out;

    // one-time resources (first call is the uncaptured correctness run)
    static bool s_init = false;
    static cudaStream_t sB;
    static cudaEvent_t evFork, evJoin;
    if (!s_init) {
        cudaStreamCreateWithFlags(&sB, cudaStreamNonBlocking);
        cudaEventCreateWithFlags(&evFork, cudaEventDisableTiming);
        cudaEventCreateWithFlags(&evJoin, cudaEventDisableTiming);
        cudaFuncSetAttribute(mma3_k<1>, cudaFuncAttributeMaxDynamicSharedMemorySize, kSmemDyn);
        cudaFuncSetAttribute(mma3_k<2>, cudaFuncAttributeMaxDynamicSharedMemorySize, kSmemDyn);
        s_init = true;
    }

    // fork weight branch onto stream B
    cudaEventRecord(evFork, 0);
    cudaStreamWaitEvent(sB, evFork, 0);
    wsplitT_k<<<128, 256, 0, sB>>>(Wv, Wo);
    mma3_k<1><<<dim3(8, 8, kNSlab), 256, kSmemDyn, sB>>>();
    reduceA_k<<<(kD * kD / 4) / 256, 256, 0, sB>>>();
    cudaEventRecord(evJoin, sB);

    // data branch on default stream (concurrent with stream B)
    k1_order_qall<<<kB + 128, 256>>>(mask, z, Wq, Wo);
    qk_gemm<<<64, 256>>>(Wk);
    attn_k<<<dim3(kL, kB), 256>>>(feats);

    // join, then final GEMM + epilogue
    cudaStreamWaitEvent(0, evJoin, 0);
    mma3_k<2><<<dim3(8, 8, kNSlab), 256, kSmemDyn>>>();
    fin_k<<<kSlab / 4 / 256, 256>>>(out, z, bo);
}

// round 16
// speedup vs baseline: 1.4237x; 1.4237x over previous
#include <cuda_runtime.h>
#include <cuda_bf16.h>
#include <math.h>
#include <stdint.h>

namespace {
constexpr int kB = 8;
constexpr int kN = 4096;
constexpr int kD = 512;
constexpr int kL = 64;
constexpr int kKS = 8;                // split-k slices for qall/qk
constexpr int kM = kB * kL;           // 512 rows through the GEMMs
constexpr int kSlab = kM * kD;        // 262144 floats per partial slab
constexpr int kNSlab = 6;             // term(3) x kz(2) partial slabs
constexpr float kInvTemp = 0.044194173824159216f; // 1/sqrt(512)
constexpr int kStageBytes = 16384;    // 8KB A + 8KB B per stage
constexpr int kSmemDyn = 4 * kStageBytes;
}

// ---------------- scratch (device globals; no allocation allowed) ----------
__device__ int   g_order[kB * kN];
__device__ int   g_nvalid[kB];
__device__ float g_qallp[kKS * kL * kD];
__device__ float g_qkp[kKS * kL * kD];
__device__ float g_denom[kM];
__device__ __nv_bfloat16 g_Uh[kM * kD],  g_Ul[kM * kD];   // bf16 split of U
__device__ __nv_bfloat16 g_Wvh[kD * kD], g_Wvl[kD * kD];
__device__ __nv_bfloat16 g_Woh[kD * kD], g_Wol[kD * kD];
__device__ __nv_bfloat16 g_Zh[kM * kD],  g_Zl[kM * kD];   // bf16 split of Zattn
__device__ float g_GP[kNSlab * kSlab];                     // partial slabs

__device__ __forceinline__ void pdl_sync() {
#if defined(__CUDA_ARCH__) && (__CUDA_ARCH__ >= 900)
    cudaGridDependencySynchronize();
#endif
}

__device__ __forceinline__ float dot4(float4 a, float4 b) {
    return a.x * b.x + a.y * b.y + a.z * b.z + a.w * b.w;
}
__device__ __forceinline__ float sum4(float4 a) { return a.x + a.y + a.z + a.w; }

__device__ __forceinline__ bool mask_at(const void* m, int idx, int kind) {
    if (kind == 1) return ((const int*)m)[idx] != 0;
    if (kind == 2) return ((const float*)m)[idx] != 0.0f;
    return ((const unsigned char*)m)[idx] != 0;
}

__device__ __forceinline__ uint32_t s2u(const void* p) {
    uint32_t a;
    asm("{ .reg .u64 t; cvta.to.shared.u64 t, %1; cvt.u32.u64 %0, t; }"
        : "=r"(a) : "l"(p));
    return a;
}
__device__ __forceinline__ void ldsm4(uint32_t addr, uint32_t r[4]) {
    asm volatile("ldmatrix.sync.aligned.m8n8.x4.shared.b16 {%0,%1,%2,%3}, [%4];"
        : "=r"(r[0]), "=r"(r[1]), "=r"(r[2]), "=r"(r[3]) : "r"(addr));
}
__device__ __forceinline__ void mma16816(float d[4], const uint32_t a[4],
                                         uint32_t b0, uint32_t b1) {
    asm volatile(
        "mma.sync.aligned.m16n8k16.row.col.f32.bf16.bf16.f32 "
        "{%0,%1,%2,%3}, {%4,%5,%6,%7}, {%8,%9}, {%0,%1,%2,%3};"
        : "+f"(d[0]), "+f"(d[1]), "+f"(d[2]), "+f"(d[3])
        : "r"(a[0]), "r"(a[1]), "r"(a[2]), "r"(a[3]), "r"(b0), "r"(b1));
}
__device__ __forceinline__ void cp16(uint32_t saddr, const void* g) {
    asm volatile("cp.async.cg.shared.global [%0], [%1], 16;"
                 :: "r"(saddr), "l"(g) : "memory");
}
__device__ __forceinline__ void cp_commit() {
    asm volatile("cp.async.commit_group;" ::: "memory");
}
template <int N>
__device__ __forceinline__ void cp_wait() {
    asm volatile("cp.async.wait_group %0;" :: "n"(N) : "memory");
}

__device__ __forceinline__ void bf16_split_store4(float4 v, __nv_bfloat16* dh,
                                                  __nv_bfloat16* dl) {
    __nv_bfloat162 h01 = __floats2bfloat162_rn(v.x, v.y);
    __nv_bfloat162 h23 = __floats2bfloat162_rn(v.z, v.w);
    float2 f01 = __bfloat1622float2(h01);
    float2 f23 = __bfloat1622float2(h23);
    __nv_bfloat162 l01 = __floats2bfloat162_rn(v.x - f01.x, v.y - f01.y);
    __nv_bfloat162 l23 = __floats2bfloat162_rn(v.z - f23.x, v.w - f23.y);
    *(__nv_bfloat162*)(dh)     = h01;
    *(__nv_bfloat162*)(dh + 2) = h23;
    *(__nv_bfloat162*)(dl)     = l01;
    *(__nv_bfloat162*)(dl + 2) = l23;
}

// ==== K1: blocks 0..7 order; 8..71 qall tiles; 72..199 weight bf16 splits ===
__global__ __launch_bounds__(256) void k1_order_qall(const void* __restrict__ mask,
                                                     const float* __restrict__ z,
                                                     const float* __restrict__ Wq,
                                                     const float* __restrict__ Wv,
                                                     const float* __restrict__ Wo) {
    const int tid = threadIdx.x;
    const int wid = tid >> 5, lane = tid & 31;

    __shared__ float Asm[64][68];
    __shared__ float Bsm[64][68];

    if (blockIdx.x < kB) {
        const int b = blockIdx.x;
        const unsigned* mw = (const unsigned*)mask;
        int iok = 1, fok = 1;
        for (int i = tid; i < 1024; i += 256) {
            unsigned v = mw[b * 1024 + i];
            iok &= (v <= 1u);
            fok &= (v == 0u || v == 0x3F800000u);
        }
        iok = __syncthreads_and(iok);
        fok = __syncthreads_and(fok);
        const int kind = iok ? 1 : (fok ? 2 : 0);

        const int base = tid * 16;
        bool v[16];
        int c = 0;
#pragma unroll
        for (int j = 0; j < 16; j++) {
            v[j] = !mask_at(mask, b * kN + base + j, kind);
            c += v[j] ? 1 : 0;
        }
        int inc = c;
#pragma unroll
        for (int o = 1; o < 32; o <<= 1) {
            int x = __shfl_up_sync(0xffffffffu, inc, o);
            if (lane >= o) inc += x;
        }
        __shared__ int wsum[8], woff[8];
        if (lane == 31) wsum[wid] = inc;
        __syncthreads();
        if (tid < 8) {
            int s = 0;
            for (int w = 0; w < 8; w++) { woff[w] = s; s += wsum[w]; }
            if (tid == 0) g_nvalid[b] = s;
        }
        __syncthreads();
        int pos = woff[wid] + inc - c;
#pragma unroll
        for (int j = 0; j < 16; j++) {
            if (v[j]) g_order[b * kN + pos++] = base + j;
        }
    } else if (blockIdx.x < kB + 64) {
        const int bid2 = blockIdx.x - kB;
        const int nt = bid2 & 7, kz = bid2 >> 3;
        const int kb = kz * 64;
        for (int jj = tid; jj < 1024; jj += 256) {
            const int l = jj >> 4, k4 = (jj & 15) * 4;
            float4 v = *(const float4*)(z + (size_t)l * kD + kb + k4);
            Asm[k4 + 0][l] = v.x; Asm[k4 + 1][l] = v.y;
            Asm[k4 + 2][l] = v.z; Asm[k4 + 3][l] = v.w;
        }
        for (int jj = tid; jj < 1024; jj += 256) {
            const int d = jj >> 4, k4 = (jj & 15) * 4;
            float4 v = *(const float4*)(Wq + (size_t)(nt * 64 + d) * kD + kb + k4);
            Bsm[k4 + 0][d] = v.x; Bsm[k4 + 1][d] = v.y;
            Bsm[k4 + 2][d] = v.z; Bsm[k4 + 3][d] = v.w;
        }
        __syncthreads();
        const int tx = tid & 15, ty = tid >> 4;
        float acc[4][4] = {};
#pragma unroll 4
        for (int k = 0; k < 64; k++) {
            float4 a = *(const float4*)&Asm[k][ty * 4];
            float4 b = *(const float4*)&Bsm[k][tx * 4];
            acc[0][0] += a.x * b.x; acc[0][1] += a.x * b.y; acc[0][2] += a.x * b.z; acc[0][3] += a.x * b.w;
            acc[1][0] += a.y * b.x; acc[1][1] += a.y * b.y; acc[1][2] += a.y * b.z; acc[1][3] += a.y * b.w;
            acc[2][0] += a.z * b.x; acc[2][1] += a.z * b.y; acc[2][2] += a.z * b.z; acc[2][3] += a.z * b.w;
            acc[3][0] += a.w * b.x; acc[3][1] += a.w * b.y; acc[3][2] += a.w * b.z; acc[3][3] += a.w * b.w;
        }
#pragma unroll
        for (int i = 0; i < 4; i++) {
            float4 v = make_float4(acc[i][0], acc[i][1], acc[i][2], acc[i][3]);
            *(float4*)&g_qallp[(size_t)kz * (kL * kD) + (size_t)(ty * 4 + i) * kD + nt * 64 + tx * 4] = v;
        }
    } else {
        const int wb = blockIdx.x - (kB + 64);
        const int which = wb >> 6, lb = wb & 63;
        const float* src = which ? Wo : Wv;
        __nv_bfloat16* dh = which ? g_Woh : g_Wvh;
        __nv_bfloat16* dl = which ? g_Wol : g_Wvl;
#pragma unroll
        for (int it = 0; it < 4; it++) {
            const int i = lb * 4096 + it * 1024 + tid * 4;
            float4 v = *(const float4*)(src + i);
            bf16_split_store4(v, dh + i, dl + i);
        }
    }
}

// ======================= K2: qk GEMM ========================================
__global__ __launch_bounds__(256) void qk_gemm(const float* __restrict__ Wk) {
    pdl_sync();
    const int tid = threadIdx.x;
    const int nt = blockIdx.x & 7, kz = blockIdx.x >> 3;
    const int kb = kz * 64;
    __shared__ float Asm[64][68];
    __shared__ float Bsm[64][68];
    for (int jj = tid; jj < 1024; jj += 256) {
        const int l = jj >> 4, k4 = (jj & 15) * 4;
        float4 v = make_float4(0.f, 0.f, 0.f, 0.f);
#pragma unroll
        for (int s = 0; s < kKS; s++) {
            float4 p = *(const float4*)&g_qallp[(size_t)s * (kL * kD) + (size_t)l * kD + kb + k4];
            v.x += p.x; v.y += p.y; v.z += p.z; v.w += p.w;
        }
        Asm[k4 + 0][l] = v.x; Asm[k4 + 1][l] = v.y;
        Asm[k4 + 2][l] = v.z; Asm[k4 + 3][l] = v.w;
    }
    for (int jj = tid; jj < 1024; jj += 256) {
        const int k = jj >> 4, e4 = (jj & 15) * 4;
        float4 v = *(const float4*)(Wk + (size_t)(kb + k) * kD + nt * 64 + e4);
        *(float4*)&Bsm[k][e4] = v;
    }
    __syncthreads();
    const int tx = tid & 15, ty = tid >> 4;
    float acc[4][4] = {};
#pragma unroll 4
    for (int k = 0; k < 64; k++) {
        float4 a = *(const float4*)&Asm[k][ty * 4];
        float4 b = *(const float4*)&Bsm[k][tx * 4];
        acc[0][0] += a.x * b.x; acc[0][1] += a.x * b.y; acc[0][2] += a.x * b.z; acc[0][3] += a.x * b.w;
        acc[1][0] += a.y * b.x; acc[1][1] += a.y * b.y; acc[1][2] += a.y * b.z; acc[1][3] += a.y * b.w;
        acc[2][0] += a.z * b.x; acc[2][1] += a.z * b.y; acc[2][2] += a.z * b.z; acc[2][3] += a.z * b.w;
        acc[3][0] += a.w * b.x; acc[3][1] += a.w * b.y; acc[3][2] += a.w * b.z; acc[3][3] += a.w * b.w;
    }
#pragma unroll
    for (int i = 0; i < 4; i++) {
        float4 v = make_float4(acc[i][0], acc[i][1], acc[i][2], acc[i][3]);
        *(float4*)&g_qkp[(size_t)(kz * kL + ty * 4 + i) * kD + nt * 64 + tx * 4] = v;
    }
}

// ============ K3: fused LN + logits + segment softmax (bf16-split out) ======
__global__ __launch_bounds__(256) void attn_k(const float* __restrict__ feats) {
    pdl_sync();
    const int l = blockIdx.x, b = blockIdx.y;
    const int tid = threadIdx.x, wid = tid >> 5, lane = tid & 31;

    __shared__ float qk_s[kD];
    __shared__ float s_part[8][kD];
    __shared__ float den_part[8];

    for (int e = tid; e < kD; e += 256) {
        float s = 0.f;
#pragma unroll
        for (int ks = 0; ks < kKS; ks++) s += g_qkp[(size_t)(ks * kL + l) * kD + e];
        qk_s[e] = s;
    }
    __syncthreads();

    float4 qk4[4];
    float qks = 0.f;
#pragma unroll
    for (int q = 0; q < 4; q++) {
        qk4[q] = *(const float4*)&qk_s[(lane + 32 * q) * 4];
        qks += sum4(qk4[q]);
    }
#pragma unroll
    for (int o = 16; o; o >>= 1) qks += __shfl_xor_sync(0xffffffffu, qks, o);

    const int nv = g_nvalid[b];
    int segsz = nv / kL; if (segsz < 1) segsz = 1;
    const int n_used = min(nv, kL * segsz);
    const int t0 = l * segsz;
    const int t1 = min(t0 + segsz, n_used);

    float4 sac[4];
#pragma unroll
    for (int q = 0; q < 4; q++) sac[q] = make_float4(0.f, 0.f, 0.f, 0.f);
    float dac = 0.f;

    int t = t0 + wid;
    int o_nxt = (t + 8 < t1) ? g_order[b * kN + t + 8] : 0;
    float4 v[4];
    if (t < t1) {
        const int o_cur = g_order[b * kN + t];
        const float4* row = (const float4*)(feats + ((size_t)b * kN + o_cur) * kD);
#pragma unroll
        for (int q = 0; q < 4; q++) v[q] = row[lane + 32 * q];
    }
    for (; t < t1; t += 8) {
        const int tn = t + 8;
        float4 vn[4];
        if (tn < t1) {
            const float4* rown = (const float4*)(feats + ((size_t)b * kN + o_nxt) * kD);
#pragma unroll
            for (int q = 0; q < 4; q++) vn[q] = rown[lane + 32 * q];
        }
        const int o_n2 = (tn + 8 < t1) ? g_order[b * kN + tn + 8] : 0;

        float sm = 0.f, sq = 0.f, dt = 0.f;
#pragma unroll
        for (int q = 0; q < 4; q++) {
            sm += sum4(v[q]);
            sq += dot4(v[q], v[q]);
            dt += dot4(v[q], qk4[q]);
        }
#pragma unroll
        for (int o = 16; o; o >>= 1) {
            sm += __shfl_xor_sync(0xffffffffu, sm, o);
            sq += __shfl_xor_sync(0xffffffffu, sq, o);
            dt += __shfl_xor_sync(0xffffffffu, dt, o);
        }
        const float mu = sm * (1.0f / kD);
        const float var = sq * (1.0f / kD) - mu * mu;
        const float rstd = rsqrtf(var + 1e-5f);
        float logit = (dt - mu * qks) * rstd * kInvTemp;
        logit = fminf(5.0f, fmaxf(-5.0f, logit));
        const float w = __expf(logit - 5.0f);
        const float wr = w * rstd;
        const float wm = wr * mu;
#pragma unroll
        for (int q = 0; q < 4; q++) {
            sac[q].x += wr * v[q].x - wm;
            sac[q].y += wr * v[q].y - wm;
            sac[q].z += wr * v[q].z - wm;
            sac[q].w += wr * v[q].w - wm;
        }
        dac += w;
        if (tn < t1) {
#pragma unroll
            for (int q = 0; q < 4; q++) v[q] = vn[q];
        }
        o_nxt = o_n2;
    }

#pragma unroll
    for (int q = 0; q < 4; q++)
        *(float4*)&s_part[wid][(lane + 32 * q) * 4] = sac[q];
    if (lane == 0) den_part[wid] = dac;
    __syncthreads();

    float den = 0.f;
#pragma unroll
    for (int w = 0; w < 8; w++) den += den_part[w];

    const int m = b * kL + l;
    const float inv = (den > 0.f) ? (1.0f / den) : 0.f;
    for (int e = tid; e < kD; e += 256) {
        float s = 0.f;
#pragma unroll
        for (int w = 0; w < 8; w++) s += s_part[w][e];
        const float v2 = s * inv;
        __nv_bfloat16 h = __float2bfloat16(v2);
        g_Uh[(size_t)m * kD + e] = h;
        g_Ul[(size_t)m * kD + e] = __float2bfloat16(v2 - __bfloat162float(h));
    }
    if (tid == 0) g_denom[m] = den;
}

// ====== K4/K6: HMMA term+K split GEMM — grid (8,8,6), fully prefetched ======
// z-slice s: term t = s>>1 (0 AhBh, 1 AhBl, 2 AlBh), kz = s&1 (K half).
// Each CTA: 64x64 tile, K=256 = 4 chunks, all stages loaded, ONE barrier.
template <int G>
__global__ __launch_bounds__(256) void mma3_k() {
    pdl_sync();
    extern __shared__ __align__(16) uint8_t sm[];   // 4 x (8KB A + 8KB B)
    const int tid = threadIdx.x, wid = tid >> 5, lane = tid & 31;
    const int nt = blockIdx.x, mt = blockIdx.y, zs = blockIdx.z;
    const int t = zs >> 1, kz = zs & 1;

    const __nv_bfloat16* Ahg = (G == 1) ? g_Uh : g_Zh;
    const __nv_bfloat16* Alg = (G == 1) ? g_Ul : g_Zl;
    const __nv_bfloat16* Bhg = (G == 1) ? g_Wvh : g_Woh;
    const __nv_bfloat16* Blg = (G == 1) ? g_Wvl : g_Wol;
    const __nv_bfloat16* A = ((t < 2) ? Ahg : Alg) + (size_t)(mt * 64) * kD + kz * 256;
    const __nv_bfloat16* Bw = ((t == 1) ? Blg : Bhg) + (size_t)(nt * 64) * kD + kz * 256;

    const int lr0 = tid >> 3, lj = tid & 7;
    const int lr1 = lr0 + 32;
    const uint32_t sw0 = lr0 * 128 + ((lj ^ (lr0 & 7)) << 4);
    const uint32_t sw1 = lr1 * 128 + ((lj ^ (lr1 & 7)) << 4);
    const uint32_t smu = s2u(sm);

#pragma unroll
    for (int c = 0; c < 4; c++) {
        const uint32_t base = smu + c * kStageBytes;
        const int kk = c * 64;
        cp16(base + sw0,        A  + (size_t)lr0 * kD + kk + lj * 8);
        cp16(base + sw1,        A  + (size_t)lr1 * kD + kk + lj * 8);
        cp16(base + 8192 + sw0, Bw + (size_t)lr0 * kD + kk + lj * 8);
        cp16(base + 8192 + sw1, Bw + (size_t)lr1 * kD + kk + lj * 8);
    }
    cp_commit();

    const int wm = (wid >> 2) << 5, wn = (wid & 3) << 4;
    const int a_r0 = wm + (lane & 15);
    const int a_r1 = a_r0 + 16;
    const int a_cadd = lane >> 4;
    const int b_r = wn + (lane & 7) + ((lane >> 4) << 3);
    const int b_cadd = (lane >> 3) & 1;

    float acc[2][2][4] = {};

    cp_wait<0>();
    __syncthreads();   // the only barrier: all 4 stages resident, never reused

#pragma unroll
    for (int c = 0; c < 4; c++) {
        const uint32_t Abase = smu + c * kStageBytes;
        const uint32_t Bbase = Abase + 8192;
#pragma unroll
        for (int ks = 0; ks < 4; ks++) {
            uint32_t a0[4], a1[4], bb[4];
            const int ch = 2 * ks;
            ldsm4(Abase + a_r0 * 128 + (((ch + a_cadd) ^ (a_r0 & 7)) << 4), a0);
            ldsm4(Abase + a_r1 * 128 + (((ch + a_cadd) ^ (a_r1 & 7)) << 4), a1);
            ldsm4(Bbase + b_r * 128 + (((ch + b_cadd) ^ (b_r & 7)) << 4), bb);
            mma16816(acc[0][0], a0, bb[0], bb[1]);
            mma16816(acc[0][1], a0, bb[2], bb[3]);
            mma16816(acc[1][0], a1, bb[0], bb[1]);
            mma16816(acc[1][1], a1, bb[2], bb[3]);
        }
    }

    float* P = g_GP + (size_t)zs * kSlab;
    const int g = lane >> 2, tg = lane & 3;
#pragma unroll
    for (int mf = 0; mf < 2; mf++) {
#pragma unroll
        for (int rr = 0; rr < 2; rr++) {
            const int m = mt * 64 + wm + mf * 16 + g + rr * 8;
#pragma unroll
            for (int nf = 0; nf < 2; nf++) {
                const int n = nt * 64 + wn + nf * 8 + tg * 2;
                *(float2*)(P + (size_t)m * kD + n) =
                    make_float2(acc[mf][nf][rr * 2 + 0], acc[mf][nf][rr * 2 + 1]);
            }
        }
    }
}

// ============ K5: reduce slabs -> Zattn bf16 split (+ empty-seg repl) =======
__global__ __launch_bounds__(256) void reduce1_k(const float* __restrict__ z) {
    pdl_sync();
    const int idx = blockIdx.x * 256 + threadIdx.x;  // float4 index
    const int m = idx >> 7, c4 = idx & 127;
    float4 v;
    if (g_denom[m] > 0.f) {
        v = make_float4(0.f, 0.f, 0.f, 0.f);
#pragma unroll
        for (int s = 0; s < kNSlab; s++) {
            float4 p = ((const float4*)g_GP)[(size_t)s * (kSlab / 4) + idx];
            v.x += p.x; v.y += p.y; v.z += p.z; v.w += p.w;
        }
    } else {
        v = ((const float4*)(z + (size_t)(m & (kL - 1)) * kD))[c4];
    }
    bf16_split_store4(v, g_Zh + idx * 4, g_Zl + idx * 4);
}

// ============ K7: final reduce + bias + sample replacement ==================
__global__ __launch_bounds__(256) void fin_k(float* __restrict__ out,
                                             const float* __restrict__ z,
                                             const float* __restrict__ bo) {
    pdl_sync();
    const int idx = blockIdx.x * 256 + threadIdx.x;  // float4 index
    const int m = idx >> 7, c4 = idx & 127;
    float4 v;
    if (g_nvalid[m >> 6] == 0) {
        v = ((const float4*)(z + (size_t)(m & (kL - 1)) * kD))[c4];
    } else {
        v = ((const float4*)bo)[c4];
#pragma unroll
        for (int s = 0; s < kNSlab; s++) {
            float4 p = ((const float4*)g_GP)[(size_t)s * (kSlab / 4) + idx];
            v.x += p.x; v.y += p.y; v.z += p.z; v.w += p.w;
        }
    }
    ((float4*)out)[idx] = v;
}

// ---------------------------------------------------------------------------
template <typename F, typename... Args>
static inline void launch_pdl(F func, dim3 grid, dim3 block, size_t smem,
                              Args... args) {
    cudaLaunchConfig_t cfg = {};
    cfg.gridDim = grid;
    cfg.blockDim = block;
    cfg.dynamicSmemBytes = smem;
    cfg.stream = 0;
    cudaLaunchAttribute attr[1];
    attr[0].id = cudaLaunchAttributeProgrammaticStreamSerialization;
    attr[0].val.programmaticStreamSerializationAllowed = 1;
    cfg.attrs = attr;
    cfg.numAttrs = 1;
    cudaLaunchKernelEx(&cfg, func, args...);
}

extern "C" void kernel_launch(void* const* d_in, const int* in_sizes, int n_in,
                              void* d_out, int out_size) {
    (void)in_sizes; (void)n_in; (void)out_size;
    const float* feats = (const float*)d_in[0];
    // d_in[1] = coords (unused by the reference output)
    const void*  mask  = d_in[2];
    const float* z     = (const float*)d_in[3];
    const float* Wq    = (const float*)d_in[4];
    const float* Wk    = (const float*)d_in[5];
    const float* Wv    = (const float*)d_in[6];
    const float* Wo    = (const float*)d_in[7];
    const float* bo    = (const float*)d_in[8];
    float* out = (float*)d_out;

    cudaFuncSetAttribute(mma3_k<1>, cudaFuncAttributeMaxDynamicSharedMemorySize, kSmemDyn);
    cudaFuncSetAttribute(mma3_k<2>, cudaFuncAttributeMaxDynamicSharedMemorySize, kSmemDyn);

    k1_order_qall<<<kB + 64 + 128, 256>>>(mask, z, Wq, Wv, Wo);
    launch_pdl(qk_gemm, dim3(64), dim3(256), 0, Wk);
    launch_pdl(attn_k, dim3(kL, kB), dim3(256), 0, feats);
    launch_pdl(mma3_k<1>, dim3(8, 8, 6), dim3(256), (size_t)kSmemDyn);
    launch_pdl(reduce1_k, dim3(kSlab / 4 / 256), dim3(256), 0, z);
    launch_pdl(mma3_k<2>, dim3(8, 8, 6), dim3(256), (size_t)kSmemDyn);
    launch_pdl(fin_k, dim3(kSlab / 4 / 256), dim3(256), 0, out, z, bo);
}